// round 1
// baseline (speedup 1.0000x reference)
#include <cuda_runtime.h>
#include <math.h>

#define INP   2048
#define MEM   4096
#define NSPLIT 16
#define ICHUNK (INP/NSPLIT)   // 128
#define MCHUNK (MEM/NSPLIT)   // 256
#define M4    (MEM/4)         // 1024

// scratch (allocation-free rule: __device__ globals)
__device__ float g_partial[NSPLIT * 4 * MEM];   // [split][gate][j]
__device__ float g_ht[MEM];

// ---------------------------------------------------------------------------
// Kernel 1: z-partials. Each thread owns 4 adjacent output columns (float4).
// grid = (MEM/1024 = 4 j-chunks, 4 gates, NSPLIT i-splits), block = 256.
// h/c GEMV loops run only when is_reset == 0 (exact per reference semantics).
// ---------------------------------------------------------------------------
__global__ void __launch_bounds__(256)
gemv_kernel(const float* __restrict__ x,
            const float* __restrict__ h0,
            const float* __restrict__ c0,
            const float* __restrict__ Wx0, const float* __restrict__ Wx1,
            const float* __restrict__ Wx2, const float* __restrict__ Wx3,
            const float* __restrict__ Wh0, const float* __restrict__ Wh1,
            const float* __restrict__ Wh2, const float* __restrict__ Wh3,
            const float* __restrict__ Wc0, const float* __restrict__ Wc1,
            const float* __restrict__ Wc2,
            const int*   __restrict__ is_reset_p)
{
    __shared__ float sv[MCHUNK];   // 256 floats: reused for x-, h-, c-chunks

    const int t     = threadIdx.x;
    const int j4    = blockIdx.x * 256 + t;   // float4 column index
    const int gate  = blockIdx.y;
    const int split = blockIdx.z;
    const int reset = *is_reset_p;

    const float* Wx = (gate == 0) ? Wx0 : (gate == 1) ? Wx1 : (gate == 2) ? Wx2 : Wx3;

    float4 acc = make_float4(0.f, 0.f, 0.f, 0.f);

    // ---- x @ Wx contribution ----
    {
        const int i0 = split * ICHUNK;
        if (t < ICHUNK) sv[t] = x[i0 + t];
        __syncthreads();
        const float4* Wp = (const float4*)Wx + (size_t)i0 * M4 + j4;
        #pragma unroll 8
        for (int i = 0; i < ICHUNK; ++i) {
            float4 w = Wp[(size_t)i * M4];
            float  v = sv[i];
            acc.x += v * w.x; acc.y += v * w.y;
            acc.z += v * w.z; acc.w += v * w.w;
        }
    }

    // ---- h @ Wh and c @ Wc contributions (skipped when reset: h=c=0) ----
    if (!reset) {
        const float* Wh = (gate == 0) ? Wh0 : (gate == 1) ? Wh1 : (gate == 2) ? Wh2 : Wh3;
        const int m0 = split * MCHUNK;

        __syncthreads();
        sv[t] = h0[m0 + t];
        __syncthreads();
        {
            const float4* Wp = (const float4*)Wh + (size_t)m0 * M4 + j4;
            #pragma unroll 8
            for (int m = 0; m < MCHUNK; ++m) {
                float4 w = Wp[(size_t)m * M4];
                float  v = sv[m];
                acc.x += v * w.x; acc.y += v * w.y;
                acc.z += v * w.z; acc.w += v * w.w;
            }
        }

        if (gate < 3) {
            const float* Wc = (gate == 0) ? Wc0 : (gate == 1) ? Wc1 : Wc2;
            __syncthreads();
            sv[t] = c0[m0 + t];
            __syncthreads();
            const float4* Wp = (const float4*)Wc + (size_t)m0 * M4 + j4;
            #pragma unroll 8
            for (int m = 0; m < MCHUNK; ++m) {
                float4 w = Wp[(size_t)m * M4];
                float  v = sv[m];
                acc.x += v * w.x; acc.y += v * w.y;
                acc.z += v * w.z; acc.w += v * w.w;
            }
        }
    }

    ((float4*)g_partial)[(size_t)(split * 4 + gate) * M4 + j4] = acc;
}

// ---------------------------------------------------------------------------
// Kernel 2: reduce partials + bias, apply gates, produce h_t.
// ---------------------------------------------------------------------------
__global__ void __launch_bounds__(256)
gates_kernel(const float* __restrict__ c0,
             const float* __restrict__ b_ig, const float* __restrict__ b_fg,
             const float* __restrict__ b_og, const float* __restrict__ b_in,
             const int*   __restrict__ is_reset_p)
{
    const int j = blockIdx.x * 256 + threadIdx.x;
    float z0 = b_ig[j], z1 = b_fg[j], z2 = b_og[j], z3 = b_in[j];
    #pragma unroll
    for (int s = 0; s < NSPLIT; ++s) {
        z0 += g_partial[(size_t)(s * 4 + 0) * MEM + j];
        z1 += g_partial[(size_t)(s * 4 + 1) * MEM + j];
        z2 += g_partial[(size_t)(s * 4 + 2) * MEM + j];
        z3 += g_partial[(size_t)(s * 4 + 3) * MEM + j];
    }
    float ig = 1.f / (1.f + __expf(-z0));
    float fg = 1.f / (1.f + __expf(-z1));
    float og = 1.f / (1.f + __expf(-z2));
    float ctn = tanhf(z3);
    float c_eff = (*is_reset_p) ? 0.f : c0[j];
    float ct = ig * ctn + fg * c_eff;
    g_ht[j] = og * tanhf(ct);
}

// ---------------------------------------------------------------------------
// Kernel 3: out[m][j] = w_hid_out[m] * h_t[j]  (4096x4096 fp32, float4 stores)
// ---------------------------------------------------------------------------
__global__ void __launch_bounds__(256)
outer_kernel(const float* __restrict__ w, float4* __restrict__ out4)
{
    const int idx = blockIdx.x * 256 + threadIdx.x;   // over 4096*1024 float4s
    const int m = idx >> 10;
    const int q = idx & 1023;
    const float wm = __ldg(&w[m]);
    float4 h = ((const float4*)g_ht)[q];
    out4[idx] = make_float4(wm * h.x, wm * h.y, wm * h.z, wm * h.w);
}

// ---------------------------------------------------------------------------
extern "C" void kernel_launch(void* const* d_in, const int* in_sizes, int n_in,
                              void* d_out, int out_size)
{
    const float* x   = (const float*)d_in[0];
    const float* h0  = (const float*)d_in[1];
    const float* c0  = (const float*)d_in[2];
    const float* w_inpgate       = (const float*)d_in[3];
    const float* w_rec_inpgate   = (const float*)d_in[4];
    const float* w_mem_inpgate   = (const float*)d_in[5];
    const float* w_inp           = (const float*)d_in[6];
    const float* w_rec_inp       = (const float*)d_in[7];
    const float* w_forgetgate    = (const float*)d_in[8];
    const float* w_rec_forgetgate= (const float*)d_in[9];
    const float* w_mem_forgetgate= (const float*)d_in[10];
    const float* w_outgate       = (const float*)d_in[11];
    const float* w_rec_outgate   = (const float*)d_in[12];
    const float* w_mem_outgate   = (const float*)d_in[13];
    const float* w_hid_out       = (const float*)d_in[14];
    const float* b_inpgate       = (const float*)d_in[15];
    const float* b_inp           = (const float*)d_in[16];
    const float* b_forgetgate    = (const float*)d_in[17];
    const float* b_outgate       = (const float*)d_in[18];
    const int*   is_reset        = (const int*)d_in[19];

    // gate order: 0=inpgate, 1=forgetgate, 2=outgate, 3=inp
    dim3 grid_g(MEM / 1024, 4, NSPLIT);
    gemv_kernel<<<grid_g, 256>>>(x, h0, c0,
        w_inpgate, w_forgetgate, w_outgate, w_inp,
        w_rec_inpgate, w_rec_forgetgate, w_rec_outgate, w_rec_inp,
        w_mem_inpgate, w_mem_forgetgate, w_mem_outgate,
        is_reset);

    gates_kernel<<<MEM / 256, 256>>>(c0, b_inpgate, b_forgetgate, b_outgate, b_inp, is_reset);

    outer_kernel<<<(MEM * M4) / 256, 256>>>(w_hid_out, (float4*)d_out);
}

// round 3
// speedup vs baseline: 1.2063x; 1.2063x over previous
#include <cuda_runtime.h>
#include <math.h>

#define INP   2048
#define MEM   4096
#define NSPLIT 32
#define ICHUNK (INP/NSPLIT)   // 64
#define MCHUNK (MEM/NSPLIT)   // 128
#define M4    (MEM/4)         // 1024

// scratch (allocation-free rule: __device__ globals)
__device__ float g_partial[NSPLIT * 4 * MEM];   // [split][gate][j]
__device__ float g_ht[MEM];

// ---------------------------------------------------------------------------
// Kernel 1: z-partials. Each thread owns 4 adjacent output columns (float4).
// grid = (M4/256 = 4 j-chunks, 4 gates, NSPLIT i-splits), block = 256.
// h/c GEMV loops run only when is_reset == 0 (exact per reference semantics).
// ---------------------------------------------------------------------------
__global__ void __launch_bounds__(256)
gemv_kernel(const float* __restrict__ x,
            const float* __restrict__ h0,
            const float* __restrict__ c0,
            const float* __restrict__ Wx0, const float* __restrict__ Wx1,
            const float* __restrict__ Wx2, const float* __restrict__ Wx3,
            const float* __restrict__ Wh0, const float* __restrict__ Wh1,
            const float* __restrict__ Wh2, const float* __restrict__ Wh3,
            const float* __restrict__ Wc0, const float* __restrict__ Wc1,
            const float* __restrict__ Wc2,
            const int*   __restrict__ is_reset_p)
{
    __shared__ float sv[MCHUNK];   // reused for x-, h-, c-chunks

    const int t     = threadIdx.x;
    const int j4    = blockIdx.x * 256 + t;   // float4 column index
    const int gate  = blockIdx.y;
    const int split = blockIdx.z;
    const int reset = *is_reset_p;

    const float* Wx = (gate == 0) ? Wx0 : (gate == 1) ? Wx1 : (gate == 2) ? Wx2 : Wx3;

    float4 acc = make_float4(0.f, 0.f, 0.f, 0.f);

    // ---- x @ Wx contribution ----
    {
        const int i0 = split * ICHUNK;
        if (t < ICHUNK) sv[t] = x[i0 + t];
        __syncthreads();
        const float4* Wp = (const float4*)Wx + (size_t)i0 * M4 + j4;
        #pragma unroll 8
        for (int i = 0; i < ICHUNK; ++i) {
            float4 w = Wp[(size_t)i * M4];
            float  v = sv[i];
            acc.x += v * w.x; acc.y += v * w.y;
            acc.z += v * w.z; acc.w += v * w.w;
        }
    }

    // ---- h @ Wh and c @ Wc contributions (skipped when reset: h=c=0) ----
    if (!reset) {
        const float* Wh = (gate == 0) ? Wh0 : (gate == 1) ? Wh1 : (gate == 2) ? Wh2 : Wh3;
        const int m0 = split * MCHUNK;

        __syncthreads();
        if (t < MCHUNK) sv[t] = h0[m0 + t];
        __syncthreads();
        {
            const float4* Wp = (const float4*)Wh + (size_t)m0 * M4 + j4;
            #pragma unroll 8
            for (int m = 0; m < MCHUNK; ++m) {
                float4 w = Wp[(size_t)m * M4];
                float  v = sv[m];
                acc.x += v * w.x; acc.y += v * w.y;
                acc.z += v * w.z; acc.w += v * w.w;
            }
        }

        if (gate < 3) {
            const float* Wc = (gate == 0) ? Wc0 : (gate == 1) ? Wc1 : Wc2;
            __syncthreads();
            if (t < MCHUNK) sv[t] = c0[m0 + t];
            __syncthreads();
            const float4* Wp = (const float4*)Wc + (size_t)m0 * M4 + j4;
            #pragma unroll 8
            for (int m = 0; m < MCHUNK; ++m) {
                float4 w = Wp[(size_t)m * M4];
                float  v = sv[m];
                acc.x += v * w.x; acc.y += v * w.y;
                acc.z += v * w.z; acc.w += v * w.w;
            }
        }
    }

    ((float4*)g_partial)[(size_t)(split * 4 + gate) * M4 + j4] = acc;
}

// ---------------------------------------------------------------------------
// Kernel 2: reduce partials + bias, apply gates, produce h_t.
// ---------------------------------------------------------------------------
__global__ void __launch_bounds__(256)
gates_kernel(const float* __restrict__ c0,
             const float* __restrict__ b_ig, const float* __restrict__ b_fg,
             const float* __restrict__ b_og, const float* __restrict__ b_in,
             const int*   __restrict__ is_reset_p)
{
    const int j = blockIdx.x * 256 + threadIdx.x;
    float z0 = b_ig[j], z1 = b_fg[j], z2 = b_og[j], z3 = b_in[j];
    #pragma unroll
    for (int s = 0; s < NSPLIT; ++s) {
        z0 += g_partial[(size_t)(s * 4 + 0) * MEM + j];
        z1 += g_partial[(size_t)(s * 4 + 1) * MEM + j];
        z2 += g_partial[(size_t)(s * 4 + 2) * MEM + j];
        z3 += g_partial[(size_t)(s * 4 + 3) * MEM + j];
    }
    float ig = 1.f / (1.f + __expf(-z0));
    float fg = 1.f / (1.f + __expf(-z1));
    float og = 1.f / (1.f + __expf(-z2));
    float ctn = tanhf(z3);
    float c_eff = (*is_reset_p) ? 0.f : c0[j];
    float ct = ig * ctn + fg * c_eff;
    g_ht[j] = og * tanhf(ct);
}

// ---------------------------------------------------------------------------
// Kernel 3: out[m][:] = w_hid_out[m] * h_t[:]. One block per row m.
// 256 threads x 4 coalesced float4 stores cover the 1024 float4s of a row.
// ---------------------------------------------------------------------------
__global__ void __launch_bounds__(256)
outer_kernel(const float* __restrict__ w, float4* __restrict__ out4)
{
    const int m = blockIdx.x;
    const int t = threadIdx.x;
    const float wm = __ldg(&w[m]);
    float4* row = out4 + (size_t)m * M4;
    const float4* h4 = (const float4*)g_ht;
    #pragma unroll
    for (int k = 0; k < 4; ++k) {
        const int q = t + k * 256;
        float4 h = h4[q];
        row[q] = make_float4(wm * h.x, wm * h.y, wm * h.z, wm * h.w);
    }
}

// ---------------------------------------------------------------------------
extern "C" void kernel_launch(void* const* d_in, const int* in_sizes, int n_in,
                              void* d_out, int out_size)
{
    const float* x   = (const float*)d_in[0];
    const float* h0  = (const float*)d_in[1];
    const float* c0  = (const float*)d_in[2];
    const float* w_inpgate       = (const float*)d_in[3];
    const float* w_rec_inpgate   = (const float*)d_in[4];
    const float* w_mem_inpgate   = (const float*)d_in[5];
    const float* w_inp           = (const float*)d_in[6];
    const float* w_rec_inp       = (const float*)d_in[7];
    const float* w_forgetgate    = (const float*)d_in[8];
    const float* w_rec_forgetgate= (const float*)d_in[9];
    const float* w_mem_forgetgate= (const float*)d_in[10];
    const float* w_outgate       = (const float*)d_in[11];
    const float* w_rec_outgate   = (const float*)d_in[12];
    const float* w_mem_outgate   = (const float*)d_in[13];
    const float* w_hid_out       = (const float*)d_in[14];
    const float* b_inpgate       = (const float*)d_in[15];
    const float* b_inp           = (const float*)d_in[16];
    const float* b_forgetgate    = (const float*)d_in[17];
    const float* b_outgate       = (const float*)d_in[18];
    const int*   is_reset        = (const int*)d_in[19];

    // gate order: 0=inpgate, 1=forgetgate, 2=outgate, 3=inp
    dim3 grid_g(M4 / 256, 4, NSPLIT);
    gemv_kernel<<<grid_g, 256>>>(x, h0, c0,
        w_inpgate, w_forgetgate, w_outgate, w_inp,
        w_rec_inpgate, w_rec_forgetgate, w_rec_outgate, w_rec_inp,
        w_mem_inpgate, w_mem_forgetgate, w_mem_outgate,
        is_reset);

    gates_kernel<<<MEM / 256, 256>>>(c0, b_inpgate, b_forgetgate, b_outgate, b_inp, is_reset);

    outer_kernel<<<MEM, 256>>>(w_hid_out, (float4*)d_out);
}